// round 2
// baseline (speedup 1.0000x reference)
#include <cuda_runtime.h>
#include <math.h>

#define B_  4
#define S_  2048
#define D_  512
#define H_  8
#define DK_ 64

// Scratch (no cudaMalloc allowed): 4 x 16 MB
__device__ float g_Qh[(size_t)B_ * H_ * S_ * DK_];
__device__ float g_Kh[(size_t)B_ * H_ * S_ * DK_];
__device__ float g_Vh[(size_t)B_ * H_ * S_ * DK_];
__device__ float g_ctx[(size_t)B_ * S_ * D_];

// C = A @ W^T + bias.  A:[8192,512] rowmajor, W:[512,512] rowmajor.
// mode 0: write head-major [B,H,S,DK]; mode 1: write plain [M,N].
// BM=BN=128, BK=8, 256 threads, 8x8 per-thread tile.
__global__ void __launch_bounds__(256) sgemm_nt(const float* __restrict__ A,
                                                const float* __restrict__ W,
                                                const float* __restrict__ bias,
                                                float* __restrict__ C, int mode)
{
    const int K = 512, N = 512;
    __shared__ float As[8][132];
    __shared__ float Bs[8][132];
    const int tid = threadIdx.x;
    const int m0 = blockIdx.y * 128;
    const int n0 = blockIdx.x * 128;
    const int tm = (tid >> 4) * 8;
    const int tn = (tid & 15) * 8;
    const int lr = tid >> 1;          // 0..127
    const int lk = (tid & 1) * 4;     // 0 or 4

    float acc[8][8];
#pragma unroll
    for (int i = 0; i < 8; i++)
#pragma unroll
        for (int j = 0; j < 8; j++) acc[i][j] = 0.f;

    const float* Ag = A + (size_t)(m0 + lr) * K + lk;
    const float* Wg = W + (size_t)(n0 + lr) * K + lk;

    for (int k0 = 0; k0 < K; k0 += 8) {
        float4 a4 = *(const float4*)(Ag + k0);
        float4 b4 = *(const float4*)(Wg + k0);
        __syncthreads();
        As[lk + 0][lr] = a4.x; As[lk + 1][lr] = a4.y;
        As[lk + 2][lr] = a4.z; As[lk + 3][lr] = a4.w;
        Bs[lk + 0][lr] = b4.x; Bs[lk + 1][lr] = b4.y;
        Bs[lk + 2][lr] = b4.z; Bs[lk + 3][lr] = b4.w;
        __syncthreads();
#pragma unroll
        for (int kk = 0; kk < 8; kk++) {
            float ra[8], rb[8];
            *(float4*)(ra)     = *(const float4*)&As[kk][tm];
            *(float4*)(ra + 4) = *(const float4*)&As[kk][tm + 4];
            *(float4*)(rb)     = *(const float4*)&Bs[kk][tn];
            *(float4*)(rb + 4) = *(const float4*)&Bs[kk][tn + 4];
#pragma unroll
            for (int i = 0; i < 8; i++)
#pragma unroll
                for (int j = 0; j < 8; j++)
                    acc[i][j] = fmaf(ra[i], rb[j], acc[i][j]);
        }
    }

#pragma unroll
    for (int i = 0; i < 8; i++) {
        const int m = m0 + tm + i;
        float v[8];
#pragma unroll
        for (int j = 0; j < 8; j++) v[j] = acc[i][j] + bias[n0 + tn + j];
        size_t base;
        if (mode == 0) {
            const int b = m >> 11, s = m & 2047;
            const int n = n0 + tn;
            const int h = n >> 6, dk = n & 63;
            base = ((size_t)(b * H_ + h) * S_ + s) * DK_ + dk;
        } else {
            base = (size_t)m * N + n0 + tn;
        }
        *(float4*)(C + base)     = make_float4(v[0], v[1], v[2], v[3]);
        *(float4*)(C + base + 4) = make_float4(v[4], v[5], v[6], v[7]);
    }
}

// Flash attention: one CTA = (b, h, 64-row q tile). Online softmax.
// Quirk faithful to reference: scores scaled by 1/H (=0.125), mask==0 -> -1e9.
__global__ void __launch_bounds__(256) attn_flash(const float* __restrict__ Qh,
                                                  const float* __restrict__ Kh,
                                                  const float* __restrict__ Vh,
                                                  const int* __restrict__ mask,
                                                  float* __restrict__ ctx)
{
    extern __shared__ float sh[];
    float* Qs = sh;                 // 64*64
    float* Ks = sh + 64 * 64;       // 64*65 (padded; aliased as P after scores)
    float* Vs = Ks + 64 * 65;       // 64*64

    const int tid = threadIdx.x;
    const int ty = tid >> 4, tx = tid & 15;
    const int q0 = blockIdx.x * 64;
    const int h  = blockIdx.y;
    const int b  = blockIdx.z;

    const float* Qg = Qh + ((size_t)(b * H_ + h) * S_ + q0) * DK_;
#pragma unroll
    for (int t = tid; t < 1024; t += 256) {
        const int row = t >> 4, c4 = (t & 15) * 4;
        *(float4*)&Qs[row * 64 + c4] = *(const float4*)(Qg + row * 64 + c4);
    }

    float m_[4], l_[4], acc[4][4];
#pragma unroll
    for (int i = 0; i < 4; i++) {
        m_[i] = -INFINITY; l_[i] = 0.f;
#pragma unroll
        for (int c = 0; c < 4; c++) acc[i][c] = 0.f;
    }

    const size_t headoff = (size_t)(b * H_ + h) * S_ * DK_;
    const size_t mask0 = (size_t)b * S_ * S_;

    for (int kt = 0; kt < S_ / 64; kt++) {
        const int k0 = kt * 64;
        const float* Kg = Kh + headoff + (size_t)k0 * DK_;
        const float* Vg = Vh + headoff + (size_t)k0 * DK_;
        __syncthreads();   // previous iter done with Ks(P)/Vs
#pragma unroll
        for (int t = tid; t < 1024; t += 256) {
            const int row = t >> 4, c4 = (t & 15) * 4;
            const float4 kv = *(const float4*)(Kg + row * 64 + c4);
            Ks[row * 65 + c4 + 0] = kv.x;
            Ks[row * 65 + c4 + 1] = kv.y;
            Ks[row * 65 + c4 + 2] = kv.z;
            Ks[row * 65 + c4 + 3] = kv.w;
            *(float4*)&Vs[row * 64 + c4] = *(const float4*)(Vg + row * 64 + c4);
        }
        __syncthreads();

        float s[4][4];
#pragma unroll
        for (int i = 0; i < 4; i++)
#pragma unroll
            for (int j = 0; j < 4; j++) s[i][j] = 0.f;

#pragma unroll 8
        for (int d = 0; d < 64; d++) {
            float rq[4], rk[4];
#pragma unroll
            for (int i = 0; i < 4; i++) rq[i] = Qs[(ty * 4 + i) * 64 + d];
#pragma unroll
            for (int j = 0; j < 4; j++) rk[j] = Ks[(tx * 4 + j) * 65 + d];
#pragma unroll
            for (int i = 0; i < 4; i++)
#pragma unroll
                for (int j = 0; j < 4; j++)
                    s[i][j] = fmaf(rq[i], rk[j], s[i][j]);
        }

        // scale by 1/H then mask (coalesced int4 from global; L2 serves reuse)
#pragma unroll
        for (int i = 0; i < 4; i++) {
            const int4 mv = *(const int4*)(mask + mask0 +
                              (size_t)(q0 + ty * 4 + i) * S_ + k0 + tx * 4);
            s[i][0] = mv.x ? s[i][0] * 0.125f : -1e9f;
            s[i][1] = mv.y ? s[i][1] * 0.125f : -1e9f;
            s[i][2] = mv.z ? s[i][2] * 0.125f : -1e9f;
            s[i][3] = mv.w ? s[i][3] * 0.125f : -1e9f;
        }

        // online softmax (registers + width-16 shuffles only)
#pragma unroll
        for (int i = 0; i < 4; i++) {
            float mt = fmaxf(fmaxf(s[i][0], s[i][1]), fmaxf(s[i][2], s[i][3]));
#pragma unroll
            for (int off = 8; off > 0; off >>= 1)
                mt = fmaxf(mt, __shfl_xor_sync(0xffffffffu, mt, off, 16));
            const float mn = fmaxf(m_[i], mt);
            const float al = __expf(m_[i] - mn);
            m_[i] = mn;
            float ps = 0.f;
#pragma unroll
            for (int j = 0; j < 4; j++) {
                const float p = __expf(s[i][j] - mn);
                s[i][j] = p; ps += p;
            }
#pragma unroll
            for (int off = 8; off > 0; off >>= 1)
                ps += __shfl_xor_sync(0xffffffffu, ps, off, 16);
            l_[i] = l_[i] * al + ps;
#pragma unroll
            for (int c = 0; c < 4; c++) acc[i][c] *= al;
        }

        __syncthreads();   // everyone done reading Ks
        float* Ps = Ks;
#pragma unroll
        for (int i = 0; i < 4; i++)
#pragma unroll
            for (int j = 0; j < 4; j++)
                Ps[(ty * 4 + i) * 65 + tx * 4 + j] = s[i][j];
        __syncthreads();

#pragma unroll 8
        for (int jj = 0; jj < 64; jj++) {
            float rp[4];
#pragma unroll
            for (int i = 0; i < 4; i++) rp[i] = Ps[(ty * 4 + i) * 65 + jj];
            float rv[4];
            *(float4*)rv = *(const float4*)&Vs[jj * 64 + tx * 4];
#pragma unroll
            for (int i = 0; i < 4; i++)
#pragma unroll
                for (int c = 0; c < 4; c++)
                    acc[i][c] = fmaf(rp[i], rv[c], acc[i][c]);
        }
    }

    // write ctx in [B,S,H,DK] so the O-projection is a plain GEMM
#pragma unroll
    for (int i = 0; i < 4; i++) {
        const float inv = 1.f / l_[i];
        const float4 o = make_float4(acc[i][0] * inv, acc[i][1] * inv,
                                     acc[i][2] * inv, acc[i][3] * inv);
        const size_t idx = ((size_t)(b * S_ + q0 + ty * 4 + i) * H_ + h) * DK_ + tx * 4;
        *(float4*)(g_ctx + idx) = o;
        (void)ctx;
    }
}

extern "C" void kernel_launch(void* const* d_in, const int* in_sizes, int n_in,
                              void* d_out, int out_size)
{
    (void)in_sizes; (void)n_in; (void)out_size;
    const float* q   = (const float*)d_in[0];
    const float* k   = (const float*)d_in[1];
    const float* v   = (const float*)d_in[2];
    const int*  mask = (const int*)d_in[3];
    const float* Wq  = (const float*)d_in[4];
    const float* bq  = (const float*)d_in[5];
    const float* Wk  = (const float*)d_in[6];
    const float* bk  = (const float*)d_in[7];
    const float* Wv  = (const float*)d_in[8];
    const float* bv  = (const float*)d_in[9];
    const float* Wo  = (const float*)d_in[10];
    const float* bo  = (const float*)d_in[11];
    float* out = (float*)d_out;

    float *Qh, *Kh, *Vh, *ctx;
    cudaGetSymbolAddress((void**)&Qh,  g_Qh);
    cudaGetSymbolAddress((void**)&Kh,  g_Kh);
    cudaGetSymbolAddress((void**)&Vh,  g_Vh);
    cudaGetSymbolAddress((void**)&ctx, g_ctx);

    const dim3 gg(4, 64), bb(256);
    sgemm_nt<<<gg, bb>>>(q, Wq, bq, Qh, 0);
    sgemm_nt<<<gg, bb>>>(k, Wk, bk, Kh, 0);
    sgemm_nt<<<gg, bb>>>(v, Wv, bv, Vh, 0);

    const int shmem = (64 * 64 + 64 * 65 + 64 * 64) * sizeof(float);  // 49408 B
    cudaFuncSetAttribute(attn_flash, cudaFuncAttributeMaxDynamicSharedMemorySize, shmem);
    attn_flash<<<dim3(32, 8, 4), 256, shmem>>>(Qh, Kh, Vh, mask, ctx);

    sgemm_nt<<<gg, bb>>>(ctx, Wo, bo, out, 1);
}

// round 3
// speedup vs baseline: 2.1903x; 2.1903x over previous
#include <cuda_runtime.h>
#include <math.h>

#define B_  4
#define S_  2048
#define D_  512
#define H_  8
#define DK_ 64

// Scratch (no cudaMalloc allowed)
__device__ float g_Qh[(size_t)B_ * H_ * S_ * DK_];
__device__ float g_Kh[(size_t)B_ * H_ * S_ * DK_];
__device__ float g_Vh[(size_t)B_ * H_ * S_ * DK_];
__device__ float g_ctx[(size_t)B_ * S_ * D_];

// ---------------- tf32 mma helpers (m16n8k8, row.col) ----------------
__device__ __forceinline__ unsigned f2tf(float f) {
    unsigned u;
    asm("cvt.rna.tf32.f32 %0, %1;" : "=r"(u) : "f"(f));
    return u;
}
__device__ __forceinline__ void mma_tf32(float* d, const unsigned* a, unsigned b0, unsigned b1) {
    asm("mma.sync.aligned.m16n8k8.row.col.f32.tf32.tf32.f32 "
        "{%0,%1,%2,%3},{%4,%5,%6,%7},{%8,%9},{%0,%1,%2,%3};"
        : "+f"(d[0]), "+f"(d[1]), "+f"(d[2]), "+f"(d[3])
        : "r"(a[0]), "r"(a[1]), "r"(a[2]), "r"(a[3]), "r"(b0), "r"(b1));
}
// Fragment layouts (lane = 4*g + t, g=lane>>2, t=lane&3):
//  A(16x8): a0=(g,t) a1=(g+8,t) a2=(g,t+4) a3=(g+8,t+4)   [row, kcol]
//  B(8x8, col-major): b0=(t, g) b1=(t+4, g)               [krow, ncol]
//  C(16x8): c0=(g,2t) c1=(g,2t+1) c2=(g+8,2t) c3=(g+8,2t+1)

// ---------------- Projection GEMM: C = A @ W^T + bias --------------------
// A:[8192,512], W:[512,512] row-major. mode 0: head-major out; mode 1: plain.
// CTA 128x128, BK=32, 256 threads = 8 warps (4m x 2n), warp tile 32x64.
__global__ void __launch_bounds__(256) gemm_tf32(const float* __restrict__ A,
                                                 const float* __restrict__ W,
                                                 const float* __restrict__ bias,
                                                 float* __restrict__ C, int mode)
{
    __shared__ unsigned As[128 * 36];
    __shared__ unsigned Bs[128 * 36];
    const int tid = threadIdx.x;
    const int warp = tid >> 5, lane = tid & 31;
    const int g = lane >> 2, t = lane & 3;
    const int wm = (warp & 3) * 32;      // warp m offset
    const int wn = (warp >> 2) * 64;     // warp n offset
    const int m0 = blockIdx.y * 128;
    const int n0 = blockIdx.x * 128;

    float acc[2][8][4];
#pragma unroll
    for (int mt = 0; mt < 2; mt++)
#pragma unroll
        for (int nt = 0; nt < 8; nt++)
#pragma unroll
            for (int i = 0; i < 4; i++) acc[mt][nt][i] = 0.f;

    for (int k0 = 0; k0 < 512; k0 += 32) {
        __syncthreads();
#pragma unroll
        for (int it = 0; it < 4; it++) {
            const int slot = tid + it * 256;          // 0..1023
            const int row = slot >> 3, c4 = (slot & 7) << 2;
            const float4 av = *(const float4*)(A + (size_t)(m0 + row) * 512 + k0 + c4);
            As[row * 36 + c4 + 0] = f2tf(av.x);
            As[row * 36 + c4 + 1] = f2tf(av.y);
            As[row * 36 + c4 + 2] = f2tf(av.z);
            As[row * 36 + c4 + 3] = f2tf(av.w);
            const float4 bv = *(const float4*)(W + (size_t)(n0 + row) * 512 + k0 + c4);
            Bs[row * 36 + c4 + 0] = f2tf(bv.x);
            Bs[row * 36 + c4 + 1] = f2tf(bv.y);
            Bs[row * 36 + c4 + 2] = f2tf(bv.z);
            Bs[row * 36 + c4 + 3] = f2tf(bv.w);
        }
        __syncthreads();
#pragma unroll
        for (int kk = 0; kk < 32; kk += 8) {
            unsigned af[2][4];
#pragma unroll
            for (int mt = 0; mt < 2; mt++) {
                const int rb = wm + mt * 16 + g;
                af[mt][0] = As[rb * 36 + kk + t];
                af[mt][1] = As[(rb + 8) * 36 + kk + t];
                af[mt][2] = As[rb * 36 + kk + t + 4];
                af[mt][3] = As[(rb + 8) * 36 + kk + t + 4];
            }
#pragma unroll
            for (int nt = 0; nt < 8; nt++) {
                const int nb = wn + nt * 8 + g;
                const unsigned b0 = Bs[nb * 36 + kk + t];
                const unsigned b1 = Bs[nb * 36 + kk + t + 4];
                mma_tf32(acc[0][nt], af[0], b0, b1);
                mma_tf32(acc[1][nt], af[1], b0, b1);
            }
        }
    }

#pragma unroll
    for (int mt = 0; mt < 2; mt++) {
        const int r = m0 + wm + mt * 16 + g;
#pragma unroll
        for (int nt = 0; nt < 8; nt++) {
            const int c = n0 + wn + nt * 8 + 2 * t;
            const float bb0 = bias[c], bb1 = bias[c + 1];
            const float2 v0 = make_float2(acc[mt][nt][0] + bb0, acc[mt][nt][1] + bb1);
            const float2 v1 = make_float2(acc[mt][nt][2] + bb0, acc[mt][nt][3] + bb1);
            size_t i0, i1;
            if (mode == 0) {
                const int b = r >> 11, s = r & 2047;
                const int h = c >> 6, dk = c & 63;
                i0 = ((size_t)(b * H_ + h) * S_ + s) * DK_ + dk;
                const int s1 = (r + 8) & 2047, b1r = (r + 8) >> 11;
                i1 = ((size_t)(b1r * H_ + h) * S_ + s1) * DK_ + dk;
            } else {
                i0 = (size_t)r * 512 + c;
                i1 = (size_t)(r + 8) * 512 + c;
            }
            *(float2*)(C + i0) = v0;
            *(float2*)(C + i1) = v1;
        }
    }
}

// ---------------- Flash attention, tf32 tensor-core ----------------
// CTA = (b, h, 64-row q tile), 4 warps, warp = 16 q rows. K tile = 64.
// smem strides: Q/K/P = 68, V = 72 (all fragment loads 32-bank conflict-free).
#define QST 68
#define KST 68
#define PST 68
#define VST 72
#define OFF_K (64 * QST)
#define OFF_V (OFF_K + 64 * KST)
#define OFF_P (OFF_V + 64 * VST)
#define SMEM_WORDS (OFF_P + 4 * 16 * PST)

__global__ void __launch_bounds__(128) attn_tf32(const float* __restrict__ Qh,
                                                 const float* __restrict__ Kh,
                                                 const float* __restrict__ Vh,
                                                 const int* __restrict__ mask,
                                                 float* __restrict__ ctx)
{
    extern __shared__ unsigned sh[];
    unsigned* Qs = sh;
    unsigned* Ks = sh + OFF_K;
    unsigned* Vs = sh + OFF_V;
    unsigned* Pw = sh + OFF_P + (threadIdx.x >> 5) * 16 * PST;

    const int tid = threadIdx.x;
    const int w = tid >> 5, lane = tid & 31;
    const int g = lane >> 2, t = lane & 3;
    const int q0 = blockIdx.x * 64;
    const int h = blockIdx.y;
    const int b = blockIdx.z;
    const size_t head = (size_t)(b * H_ + h);

    // Load Q tile, fold the 1/H score scale into Q, convert to tf32.
    const float* Qg = Qh + (head * S_ + q0) * DK_;
    for (int slot = tid; slot < 1024; slot += 128) {
        const int row = slot >> 4, c4 = (slot & 15) << 2;
        const float4 qv = *(const float4*)(Qg + row * 64 + c4);
        Qs[row * QST + c4 + 0] = f2tf(qv.x * 0.125f);
        Qs[row * QST + c4 + 1] = f2tf(qv.y * 0.125f);
        Qs[row * QST + c4 + 2] = f2tf(qv.z * 0.125f);
        Qs[row * QST + c4 + 3] = f2tf(qv.w * 0.125f);
    }

    float acc[8][4];
#pragma unroll
    for (int nt = 0; nt < 8; nt++)
#pragma unroll
        for (int i = 0; i < 4; i++) acc[nt][i] = 0.f;
    float mrow0 = -INFINITY, mrow1 = -INFINITY;
    float lrow0 = 0.f, lrow1 = 0.f;

    const int r0g = q0 + w * 16 + g;   // global q row for c0/c1
    const int r1g = r0g + 8;           // global q row for c2/c3
    const int* maskb = mask + (size_t)b * S_ * S_;

    for (int kt = 0; kt < S_ / 64; kt++) {
        const int k0 = kt * 64;
        const float* Kg = Kh + (head * S_ + k0) * DK_;
        const float* Vg = Vh + (head * S_ + k0) * DK_;
        __syncthreads();
        for (int slot = tid; slot < 1024; slot += 128) {
            const int row = slot >> 4, c4 = (slot & 15) << 2;
            const float4 kv = *(const float4*)(Kg + row * 64 + c4);
            Ks[row * KST + c4 + 0] = f2tf(kv.x);
            Ks[row * KST + c4 + 1] = f2tf(kv.y);
            Ks[row * KST + c4 + 2] = f2tf(kv.z);
            Ks[row * KST + c4 + 3] = f2tf(kv.w);
            const float4 vv = *(const float4*)(Vg + row * 64 + c4);
            Vs[row * VST + c4 + 0] = f2tf(vv.x);
            Vs[row * VST + c4 + 1] = f2tf(vv.y);
            Vs[row * VST + c4 + 2] = f2tf(vv.z);
            Vs[row * VST + c4 + 3] = f2tf(vv.w);
        }
        __syncthreads();

        // ---- S = (Q/H) @ K^T  (16x64 per warp) ----
        float sc[8][4];
#pragma unroll
        for (int nt = 0; nt < 8; nt++)
#pragma unroll
            for (int i = 0; i < 4; i++) sc[nt][i] = 0.f;

#pragma unroll
        for (int kk = 0; kk < 64; kk += 8) {
            unsigned aq[4];
            const int qb = w * 16 + g;
            aq[0] = Qs[qb * QST + kk + t];
            aq[1] = Qs[(qb + 8) * QST + kk + t];
            aq[2] = Qs[qb * QST + kk + t + 4];
            aq[3] = Qs[(qb + 8) * QST + kk + t + 4];
#pragma unroll
            for (int nt = 0; nt < 8; nt++) {
                const int kb = nt * 8 + g;
                mma_tf32(sc[nt], aq, Ks[kb * KST + kk + t], Ks[kb * KST + kk + t + 4]);
            }
        }

        // ---- mask ----
#pragma unroll
        for (int nt = 0; nt < 8; nt++) {
            const int kc = k0 + nt * 8 + 2 * t;
            const int2 m0v = *(const int2*)(maskb + (size_t)r0g * S_ + kc);
            const int2 m1v = *(const int2*)(maskb + (size_t)r1g * S_ + kc);
            sc[nt][0] = m0v.x ? sc[nt][0] : -1e9f;
            sc[nt][1] = m0v.y ? sc[nt][1] : -1e9f;
            sc[nt][2] = m1v.x ? sc[nt][2] : -1e9f;
            sc[nt][3] = m1v.y ? sc[nt][3] : -1e9f;
        }

        // ---- online softmax (two rows per thread, quad-shuffle reduce) ----
        float mt0 = -INFINITY, mt1 = -INFINITY;
#pragma unroll
        for (int nt = 0; nt < 8; nt++) {
            mt0 = fmaxf(mt0, fmaxf(sc[nt][0], sc[nt][1]));
            mt1 = fmaxf(mt1, fmaxf(sc[nt][2], sc[nt][3]));
        }
        mt0 = fmaxf(mt0, __shfl_xor_sync(0xffffffffu, mt0, 1));
        mt0 = fmaxf(mt0, __shfl_xor_sync(0xffffffffu, mt0, 2));
        mt1 = fmaxf(mt1, __shfl_xor_sync(0xffffffffu, mt1, 1));
        mt1 = fmaxf(mt1, __shfl_xor_sync(0xffffffffu, mt1, 2));
        const float mn0 = fmaxf(mrow0, mt0), mn1 = fmaxf(mrow1, mt1);
        const float al0 = __expf(mrow0 - mn0), al1 = __expf(mrow1 - mn1);
        mrow0 = mn0; mrow1 = mn1;
        float ps0 = 0.f, ps1 = 0.f;
#pragma unroll
        for (int nt = 0; nt < 8; nt++) {
            sc[nt][0] = __expf(sc[nt][0] - mn0);
            sc[nt][1] = __expf(sc[nt][1] - mn0);
            sc[nt][2] = __expf(sc[nt][2] - mn1);
            sc[nt][3] = __expf(sc[nt][3] - mn1);
            ps0 += sc[nt][0] + sc[nt][1];
            ps1 += sc[nt][2] + sc[nt][3];
        }
        ps0 += __shfl_xor_sync(0xffffffffu, ps0, 1);
        ps0 += __shfl_xor_sync(0xffffffffu, ps0, 2);
        ps1 += __shfl_xor_sync(0xffffffffu, ps1, 1);
        ps1 += __shfl_xor_sync(0xffffffffu, ps1, 2);
        lrow0 = lrow0 * al0 + ps0;
        lrow1 = lrow1 * al1 + ps1;
#pragma unroll
        for (int nt = 0; nt < 8; nt++) {
            acc[nt][0] *= al0; acc[nt][1] *= al0;
            acc[nt][2] *= al1; acc[nt][3] *= al1;
        }

        // ---- P -> per-warp smem (WAR fence vs last iter's PV reads) ----
        __syncwarp();
#pragma unroll
        for (int nt = 0; nt < 8; nt++) {
            const int col = nt * 8 + 2 * t;
            Pw[g * PST + col]           = f2tf(sc[nt][0]);
            Pw[g * PST + col + 1]       = f2tf(sc[nt][1]);
            Pw[(g + 8) * PST + col]     = f2tf(sc[nt][2]);
            Pw[(g + 8) * PST + col + 1] = f2tf(sc[nt][3]);
        }
        __syncwarp();

        // ---- acc += P @ V ----
#pragma unroll
        for (int kk = 0; kk < 64; kk += 8) {
            unsigned ap[4];
            ap[0] = Pw[g * PST + kk + t];
            ap[1] = Pw[(g + 8) * PST + kk + t];
            ap[2] = Pw[g * PST + kk + t + 4];
            ap[3] = Pw[(g + 8) * PST + kk + t + 4];
#pragma unroll
            for (int nt = 0; nt < 8; nt++) {
                mma_tf32(acc[nt], ap,
                         Vs[(kk + t) * VST + nt * 8 + g],
                         Vs[(kk + t + 4) * VST + nt * 8 + g]);
            }
        }
    }

    // ---- normalize + write ctx [B,S,H,DK] ----
    const float inv0 = 1.f / lrow0, inv1 = 1.f / lrow1;
#pragma unroll
    for (int nt = 0; nt < 8; nt++) {
        const int dk = nt * 8 + 2 * t;
        const size_t i0 = ((size_t)(b * S_ + r0g) * H_ + h) * DK_ + dk;
        const size_t i1 = ((size_t)(b * S_ + r1g) * H_ + h) * DK_ + dk;
        *(float2*)(ctx + i0) = make_float2(acc[nt][0] * inv0, acc[nt][1] * inv0);
        *(float2*)(ctx + i1) = make_float2(acc[nt][2] * inv1, acc[nt][3] * inv1);
    }
}

extern "C" void kernel_launch(void* const* d_in, const int* in_sizes, int n_in,
                              void* d_out, int out_size)
{
    (void)in_sizes; (void)n_in; (void)out_size;
    const float* q   = (const float*)d_in[0];
    const float* k   = (const float*)d_in[1];
    const float* v   = (const float*)d_in[2];
    const int*  mask = (const int*)d_in[3];
    const float* Wq  = (const float*)d_in[4];
    const float* bq  = (const float*)d_in[5];
    const float* Wk  = (const float*)d_in[6];
    const float* bk  = (const float*)d_in[7];
    const float* Wv  = (const float*)d_in[8];
    const float* bv  = (const float*)d_in[9];
    const float* Wo  = (const float*)d_in[10];
    const float* bo  = (const float*)d_in[11];
    float* out = (float*)d_out;

    float *Qh, *Kh, *Vh, *ctx;
    cudaGetSymbolAddress((void**)&Qh,  g_Qh);
    cudaGetSymbolAddress((void**)&Kh,  g_Kh);
    cudaGetSymbolAddress((void**)&Vh,  g_Vh);
    cudaGetSymbolAddress((void**)&ctx, g_ctx);

    const dim3 gg(4, 64), bb(256);
    gemm_tf32<<<gg, bb>>>(q, Wq, bq, Qh, 0);
    gemm_tf32<<<gg, bb>>>(k, Wk, bk, Kh, 0);
    gemm_tf32<<<gg, bb>>>(v, Wv, bv, Vh, 0);

    const int shmem = SMEM_WORDS * sizeof(unsigned);   // 70656 B
    cudaFuncSetAttribute(attn_tf32, cudaFuncAttributeMaxDynamicSharedMemorySize, shmem);
    attn_tf32<<<dim3(32, 8, 4), 128, shmem>>>(Qh, Kh, Vh, mask, ctx);

    gemm_tf32<<<gg, bb>>>(ctx, Wo, bo, out, 1);
}

// round 4
// speedup vs baseline: 2.8078x; 1.2819x over previous
#include <cuda_runtime.h>
#include <math.h>

#define B_  4
#define S_  2048
#define D_  512
#define H_  8
#define DK_ 64

// Scratch (no cudaMalloc allowed)
__device__ float g_Qh[(size_t)B_ * H_ * S_ * DK_];
__device__ float g_Kh[(size_t)B_ * H_ * S_ * DK_];
__device__ float g_Vh[(size_t)B_ * H_ * S_ * DK_];
__device__ float g_ctx[(size_t)B_ * S_ * D_];

// ---------------- tf32 mma helpers (m16n8k8, row.col) ----------------
__device__ __forceinline__ unsigned f2tf(float f) {
    unsigned u;
    asm("cvt.rna.tf32.f32 %0, %1;" : "=r"(u) : "f"(f));
    return u;
}
__device__ __forceinline__ void mma_tf32(float* d, const unsigned* a, unsigned b0, unsigned b1) {
    asm("mma.sync.aligned.m16n8k8.row.col.f32.tf32.tf32.f32 "
        "{%0,%1,%2,%3},{%4,%5,%6,%7},{%8,%9},{%0,%1,%2,%3};"
        : "+f"(d[0]), "+f"(d[1]), "+f"(d[2]), "+f"(d[3])
        : "r"(a[0]), "r"(a[1]), "r"(a[2]), "r"(a[3]), "r"(b0), "r"(b1));
}
// Fragment layouts (lane = 4*g + t, g=lane>>2, t=lane&3):
//  A(16x8): a0=(g,t) a1=(g+8,t) a2=(g,t+4) a3=(g+8,t+4)   [row, kcol]
//  B(8x8, col-major): b0=(t, g) b1=(t+4, g)               [krow, ncol]
//  C(16x8): c0=(g,2t) c1=(g,2t+1) c2=(g+8,2t) c3=(g+8,2t+1)

// ---------------- Projection GEMM: C = A @ W^T + bias --------------------
__global__ void __launch_bounds__(256) gemm_tf32(const float* __restrict__ A,
                                                 const float* __restrict__ W,
                                                 const float* __restrict__ bias,
                                                 float* __restrict__ C, int mode)
{
    __shared__ unsigned As[128 * 36];
    __shared__ unsigned Bs[128 * 36];
    const int tid = threadIdx.x;
    const int warp = tid >> 5, lane = tid & 31;
    const int g = lane >> 2, t = lane & 3;
    const int wm = (warp & 3) * 32;
    const int wn = (warp >> 2) * 64;
    const int m0 = blockIdx.y * 128;
    const int n0 = blockIdx.x * 128;

    float acc[2][8][4];
#pragma unroll
    for (int mt = 0; mt < 2; mt++)
#pragma unroll
        for (int nt = 0; nt < 8; nt++)
#pragma unroll
            for (int i = 0; i < 4; i++) acc[mt][nt][i] = 0.f;

    for (int k0 = 0; k0 < 512; k0 += 32) {
        __syncthreads();
#pragma unroll
        for (int it = 0; it < 4; it++) {
            const int slot = tid + it * 256;
            const int row = slot >> 3, c4 = (slot & 7) << 2;
            const float4 av = *(const float4*)(A + (size_t)(m0 + row) * 512 + k0 + c4);
            As[row * 36 + c4 + 0] = f2tf(av.x);
            As[row * 36 + c4 + 1] = f2tf(av.y);
            As[row * 36 + c4 + 2] = f2tf(av.z);
            As[row * 36 + c4 + 3] = f2tf(av.w);
            const float4 bv = *(const float4*)(W + (size_t)(n0 + row) * 512 + k0 + c4);
            Bs[row * 36 + c4 + 0] = f2tf(bv.x);
            Bs[row * 36 + c4 + 1] = f2tf(bv.y);
            Bs[row * 36 + c4 + 2] = f2tf(bv.z);
            Bs[row * 36 + c4 + 3] = f2tf(bv.w);
        }
        __syncthreads();
#pragma unroll
        for (int kk = 0; kk < 32; kk += 8) {
            unsigned af[2][4];
#pragma unroll
            for (int mt = 0; mt < 2; mt++) {
                const int rb = wm + mt * 16 + g;
                af[mt][0] = As[rb * 36 + kk + t];
                af[mt][1] = As[(rb + 8) * 36 + kk + t];
                af[mt][2] = As[rb * 36 + kk + t + 4];
                af[mt][3] = As[(rb + 8) * 36 + kk + t + 4];
            }
#pragma unroll
            for (int nt = 0; nt < 8; nt++) {
                const int nb = wn + nt * 8 + g;
                const unsigned b0 = Bs[nb * 36 + kk + t];
                const unsigned b1 = Bs[nb * 36 + kk + t + 4];
                mma_tf32(acc[0][nt], af[0], b0, b1);
                mma_tf32(acc[1][nt], af[1], b0, b1);
            }
        }
    }

#pragma unroll
    for (int mt = 0; mt < 2; mt++) {
        const int r = m0 + wm + mt * 16 + g;
#pragma unroll
        for (int nt = 0; nt < 8; nt++) {
            const int c = n0 + wn + nt * 8 + 2 * t;
            const float bb0 = bias[c], bb1 = bias[c + 1];
            const float2 v0 = make_float2(acc[mt][nt][0] + bb0, acc[mt][nt][1] + bb1);
            const float2 v1 = make_float2(acc[mt][nt][2] + bb0, acc[mt][nt][3] + bb1);
            size_t i0, i1;
            if (mode == 0) {
                const int b = r >> 11, s = r & 2047;
                const int h = c >> 6, dk = c & 63;
                i0 = ((size_t)(b * H_ + h) * S_ + s) * DK_ + dk;
                const int s1 = (r + 8) & 2047, b1r = (r + 8) >> 11;
                i1 = ((size_t)(b1r * H_ + h) * S_ + s1) * DK_ + dk;
            } else {
                i0 = (size_t)r * 512 + c;
                i1 = (size_t)(r + 8) * 512 + c;
            }
            *(float2*)(C + i0) = v0;
            *(float2*)(C + i1) = v1;
        }
    }
}

// ---------------- Flash attention, tf32 tensor-core ----------------
// CTA = (b, h, 64-row q tile), 4 warps, warp = 16 q rows. K tile = 64.
// No P smem: S C-fragment -> P A-fragment via in-quad shuffles.
// smem = Q(64x68) + K(64x68) + V(64x72) = 53248 B -> 4 CTAs/SM.
#define QST 68
#define KST 68
#define VST 72
#define OFF_K (64 * QST)
#define OFF_V (OFF_K + 64 * KST)
#define SMEM_WORDS (OFF_V + 64 * VST)

// exp2-domain scale: 1/H * log2(e)
#define QSCALE (0.125f * 1.44269504088896340736f)

__global__ void __launch_bounds__(128, 4) attn_tf32(const float* __restrict__ Qh,
                                                    const float* __restrict__ Kh,
                                                    const float* __restrict__ Vh,
                                                    const int* __restrict__ mask,
                                                    float* __restrict__ ctx)
{
    extern __shared__ unsigned sh[];
    unsigned* Qs = sh;
    unsigned* Ks = sh + OFF_K;
    unsigned* Vs = sh + OFF_V;

    const int tid = threadIdx.x;
    const int w = tid >> 5, lane = tid & 31;
    const int g = lane >> 2, t = lane & 3;
    const int q0 = blockIdx.x * 64;
    const int h = blockIdx.y;
    const int b = blockIdx.z;
    const size_t head = (size_t)(b * H_ + h);

    // Load Q tile; fold 1/H * log2(e) into Q (scores land in exp2 domain).
    const float* Qg = Qh + (head * S_ + q0) * DK_;
    for (int slot = tid; slot < 1024; slot += 128) {
        const int row = slot >> 4, c4 = (slot & 15) << 2;
        const float4 qv = *(const float4*)(Qg + row * 64 + c4);
        Qs[row * QST + c4 + 0] = f2tf(qv.x * QSCALE);
        Qs[row * QST + c4 + 1] = f2tf(qv.y * QSCALE);
        Qs[row * QST + c4 + 2] = f2tf(qv.z * QSCALE);
        Qs[row * QST + c4 + 3] = f2tf(qv.w * QSCALE);
    }

    float acc[8][4];
#pragma unroll
    for (int nt = 0; nt < 8; nt++)
#pragma unroll
        for (int i = 0; i < 4; i++) acc[nt][i] = 0.f;
    float mrow0 = -INFINITY, mrow1 = -INFINITY;
    float lrow0 = 0.f, lrow1 = 0.f;

    const int r0g = q0 + w * 16 + g;
    const int r1g = r0g + 8;
    const int* maskb = mask + (size_t)b * S_ * S_;
    const int sbase = lane & 28;
    const int src0 = sbase | (t >> 1);        // quad-local source for col t
    const int src2 = sbase | ((t >> 1) + 2);  // quad-local source for col t+4

    for (int kt = 0; kt < S_ / 64; kt++) {
        const int k0 = kt * 64;
        const float* Kg = Kh + (head * S_ + k0) * DK_;
        const float* Vg = Vh + (head * S_ + k0) * DK_;
        __syncthreads();   // previous iter done reading Ks/Vs
        for (int slot = tid; slot < 1024; slot += 128) {
            const int row = slot >> 4, c4 = (slot & 15) << 2;
            const float4 kv = *(const float4*)(Kg + row * 64 + c4);
            Ks[row * KST + c4 + 0] = f2tf(kv.x);
            Ks[row * KST + c4 + 1] = f2tf(kv.y);
            Ks[row * KST + c4 + 2] = f2tf(kv.z);
            Ks[row * KST + c4 + 3] = f2tf(kv.w);
            const float4 vv = *(const float4*)(Vg + row * 64 + c4);
            Vs[row * VST + c4 + 0] = f2tf(vv.x);
            Vs[row * VST + c4 + 1] = f2tf(vv.y);
            Vs[row * VST + c4 + 2] = f2tf(vv.z);
            Vs[row * VST + c4 + 3] = f2tf(vv.w);
        }
        __syncthreads();

        // ---- S = (Q*scale) @ K^T  (16x64 per warp) ----
        float sc[8][4];
#pragma unroll
        for (int nt = 0; nt < 8; nt++)
#pragma unroll
            for (int i = 0; i < 4; i++) sc[nt][i] = 0.f;

#pragma unroll
        for (int kk = 0; kk < 64; kk += 8) {
            unsigned aq[4];
            const int qb = w * 16 + g;
            aq[0] = Qs[qb * QST + kk + t];
            aq[1] = Qs[(qb + 8) * QST + kk + t];
            aq[2] = Qs[qb * QST + kk + t + 4];
            aq[3] = Qs[(qb + 8) * QST + kk + t + 4];
#pragma unroll
            for (int nt = 0; nt < 8; nt++) {
                const int kb = nt * 8 + g;
                mma_tf32(sc[nt], aq, Ks[kb * KST + kk + t], Ks[kb * KST + kk + t + 4]);
            }
        }

        // ---- mask (scores already in exp2 domain; -1e9 -> exp2 == 0) ----
#pragma unroll
        for (int nt = 0; nt < 8; nt++) {
            const int kc = k0 + nt * 8 + 2 * t;
            const int2 m0v = *(const int2*)(maskb + (size_t)r0g * S_ + kc);
            const int2 m1v = *(const int2*)(maskb + (size_t)r1g * S_ + kc);
            sc[nt][0] = m0v.x ? sc[nt][0] : -1e9f;
            sc[nt][1] = m0v.y ? sc[nt][1] : -1e9f;
            sc[nt][2] = m1v.x ? sc[nt][2] : -1e9f;
            sc[nt][3] = m1v.y ? sc[nt][3] : -1e9f;
        }

        // ---- online softmax in exp2 domain ----
        float mt0 = -INFINITY, mt1 = -INFINITY;
#pragma unroll
        for (int nt = 0; nt < 8; nt++) {
            mt0 = fmaxf(mt0, fmaxf(sc[nt][0], sc[nt][1]));
            mt1 = fmaxf(mt1, fmaxf(sc[nt][2], sc[nt][3]));
        }
        mt0 = fmaxf(mt0, __shfl_xor_sync(0xffffffffu, mt0, 1));
        mt0 = fmaxf(mt0, __shfl_xor_sync(0xffffffffu, mt0, 2));
        mt1 = fmaxf(mt1, __shfl_xor_sync(0xffffffffu, mt1, 1));
        mt1 = fmaxf(mt1, __shfl_xor_sync(0xffffffffu, mt1, 2));
        const float mn0 = fmaxf(mrow0, mt0), mn1 = fmaxf(mrow1, mt1);
        const float al0 = exp2f(mrow0 - mn0), al1 = exp2f(mrow1 - mn1);
        mrow0 = mn0; mrow1 = mn1;
        float ps0 = 0.f, ps1 = 0.f;
#pragma unroll
        for (int nt = 0; nt < 8; nt++) {
            sc[nt][0] = exp2f(sc[nt][0] - mn0);
            sc[nt][1] = exp2f(sc[nt][1] - mn0);
            sc[nt][2] = exp2f(sc[nt][2] - mn1);
            sc[nt][3] = exp2f(sc[nt][3] - mn1);
            ps0 += sc[nt][0] + sc[nt][1];
            ps1 += sc[nt][2] + sc[nt][3];
        }
        ps0 += __shfl_xor_sync(0xffffffffu, ps0, 1);
        ps0 += __shfl_xor_sync(0xffffffffu, ps0, 2);
        ps1 += __shfl_xor_sync(0xffffffffu, ps1, 1);
        ps1 += __shfl_xor_sync(0xffffffffu, ps1, 2);
        lrow0 = lrow0 * al0 + ps0;
        lrow1 = lrow1 * al1 + ps1;
#pragma unroll
        for (int nt = 0; nt < 8; nt++) {
            acc[nt][0] *= al0; acc[nt][1] *= al0;
            acc[nt][2] *= al1; acc[nt][3] *= al1;
        }

        // ---- acc += P @ V ; P A-fragments built by in-quad shuffles ----
        // Element P(g, 8s+c) lives in lane 4g+(c>>1), register index c&1
        // (rows g) / 2+(c&1) (rows g+8). A-frag col indices are t and t+4.
#pragma unroll
        for (int s = 0; s < 8; s++) {
            const unsigned u0 = f2tf(sc[s][0]);
            const unsigned u1 = f2tf(sc[s][1]);
            const unsigned u2 = f2tf(sc[s][2]);
            const unsigned u3 = f2tf(sc[s][3]);
            unsigned ap[4];
            const unsigned v00 = __shfl_sync(0xffffffffu, u0, src0);
            const unsigned v01 = __shfl_sync(0xffffffffu, u1, src0);
            ap[0] = (t & 1) ? v01 : v00;
            const unsigned v20 = __shfl_sync(0xffffffffu, u2, src0);
            const unsigned v21 = __shfl_sync(0xffffffffu, u3, src0);
            ap[1] = (t & 1) ? v21 : v20;
            const unsigned w00 = __shfl_sync(0xffffffffu, u0, src2);
            const unsigned w01 = __shfl_sync(0xffffffffu, u1, src2);
            ap[2] = (t & 1) ? w01 : w00;
            const unsigned w20 = __shfl_sync(0xffffffffu, u2, src2);
            const unsigned w21 = __shfl_sync(0xffffffffu, u3, src2);
            ap[3] = (t & 1) ? w21 : w20;

            const int kk = s * 8;
#pragma unroll
            for (int nt = 0; nt < 8; nt++) {
                mma_tf32(acc[nt], ap,
                         Vs[(kk + t) * VST + nt * 8 + g],
                         Vs[(kk + t + 4) * VST + nt * 8 + g]);
            }
        }
    }

    // ---- normalize + write ctx [B,S,H,DK] ----
    const float inv0 = 1.f / lrow0, inv1 = 1.f / lrow1;
#pragma unroll
    for (int nt = 0; nt < 8; nt++) {
        const int dk = nt * 8 + 2 * t;
        const size_t i0 = ((size_t)(b * S_ + r0g) * H_ + h) * DK_ + dk;
        const size_t i1 = ((size_t)(b * S_ + r1g) * H_ + h) * DK_ + dk;
        *(float2*)(ctx + i0) = make_float2(acc[nt][0] * inv0, acc[nt][1] * inv0);
        *(float2*)(ctx + i1) = make_float2(acc[nt][2] * inv1, acc[nt][3] * inv1);
    }
}

extern "C" void kernel_launch(void* const* d_in, const int* in_sizes, int n_in,
                              void* d_out, int out_size)
{
    (void)in_sizes; (void)n_in; (void)out_size;
    const float* q   = (const float*)d_in[0];
    const float* k   = (const float*)d_in[1];
    const float* v   = (const float*)d_in[2];
    const int*  mask = (const int*)d_in[3];
    const float* Wq  = (const float*)d_in[4];
    const float* bq  = (const float*)d_in[5];
    const float* Wk  = (const float*)d_in[6];
    const float* bk  = (const float*)d_in[7];
    const float* Wv  = (const float*)d_in[8];
    const float* bv  = (const float*)d_in[9];
    const float* Wo  = (const float*)d_in[10];
    const float* bo  = (const float*)d_in[11];
    float* out = (float*)d_out;

    float *Qh, *Kh, *Vh, *ctx;
    cudaGetSymbolAddress((void**)&Qh,  g_Qh);
    cudaGetSymbolAddress((void**)&Kh,  g_Kh);
    cudaGetSymbolAddress((void**)&Vh,  g_Vh);
    cudaGetSymbolAddress((void**)&ctx, g_ctx);

    const dim3 gg(4, 64), bb(256);
    gemm_tf32<<<gg, bb>>>(q, Wq, bq, Qh, 0);
    gemm_tf32<<<gg, bb>>>(k, Wk, bk, Kh, 0);
    gemm_tf32<<<gg, bb>>>(v, Wv, bv, Vh, 0);

    const int shmem = SMEM_WORDS * sizeof(unsigned);   // 53248 B
    cudaFuncSetAttribute(attn_tf32, cudaFuncAttributeMaxDynamicSharedMemorySize, shmem);
    attn_tf32<<<dim3(32, 8, 4), 128, shmem>>>(Qh, Kh, Vh, mask, ctx);

    gemm_tf32<<<gg, bb>>>(ctx, Wo, bo, out, 1);
}